// round 6
// baseline (speedup 1.0000x reference)
#include <cuda_runtime.h>
#include <cstdint>
#include <cstddef>

#define SQ 2048
#define HIDN 2048
#define NHEAD 16
#define NKVH 4
#define HDIM 128
#define QKV_N 3072
#define RECENT_W 204
#define HEAVY_K 204

// ---------------- scratch (device globals; no allocations allowed) ----------
__device__ float g_qkv[SQ * QKV_N];                 // raw qkv projections
__device__ float g_q[NHEAD * SQ * HDIM];            // rotated q, [h][s][d]
__device__ float g_k[NKVH * SQ * HDIM];             // rotated k, [h][s][d]
__device__ float g_v[NKVH * SQ * HDIM];             // v, [h][s][d]
__device__ float g_e[NHEAD * SQ * SQ];              // scores, then exp(s - rowmax)
__device__ float g_invrsum[NHEAD * SQ];             // 1 / full-causal row sum
__device__ float g_colsum[NHEAD * SQ];              // softmax column sums
__device__ float g_invrsum2[NHEAD * SQ];            // 1 / masked row sum
__device__ unsigned char g_heavy[NHEAD * SQ];       // heavy-hitter column flags
__device__ float g_attnout[SQ * HIDN];              // attention output, [s][h*128+d]

// ---------------- warp reductions ----------------
static __device__ __forceinline__ float warp_red_max(float v) {
#pragma unroll
    for (int o = 16; o > 0; o >>= 1) v = fmaxf(v, __shfl_xor_sync(0xffffffffu, v, o));
    return v;
}
static __device__ __forceinline__ float warp_red_sum(float v) {
#pragma unroll
    for (int o = 16; o > 0; o >>= 1) v += __shfl_xor_sync(0xffffffffu, v, o);
    return v;
}

// ---------------- generic fp32 GEMM: C[M,N] = A[M,K] @ B[K,N] (+bias) -------
// 128x128 block tile, 8-deep k slice, 256 threads, 8x8 per-thread micro tile.
// Grid: (N/128, M/128). M,N multiples of 128; K multiple of 8.
__global__ __launch_bounds__(256) void gemm_kernel(
    const float* __restrict__ A, int lda,
    const float* __restrict__ B, int ldb,
    const float* __restrict__ bias,
    float* __restrict__ C, int ldc, int K)
{
    __shared__ float As[8][128];
    __shared__ float Bs[8][128];
    int tid = threadIdx.x;
    int row0 = blockIdx.y * 128, col0 = blockIdx.x * 128;
    int tr = tid >> 4, tc = tid & 15;
    float acc[8][8];
#pragma unroll
    for (int y = 0; y < 8; y++)
#pragma unroll
        for (int x = 0; x < 8; x++) acc[y][x] = 0.f;

    int am = (tid * 4) >> 3, ak = (tid * 4) & 7;      // A: 128 rows x 8 k
    int bk = (tid * 4) >> 7, bn = (tid * 4) & 127;    // B: 8 k x 128 cols
    const float* Aptr = A + (size_t)(row0 + am) * lda + ak;
    const float* Bptr = B + (size_t)bk * ldb + col0 + bn;

    for (int k0 = 0; k0 < K; k0 += 8) {
        float4 a4 = *(const float4*)(Aptr + k0);
        float4 b4 = *(const float4*)(Bptr + (size_t)k0 * ldb);
        As[ak + 0][am] = a4.x; As[ak + 1][am] = a4.y;
        As[ak + 2][am] = a4.z; As[ak + 3][am] = a4.w;
        *(float4*)&Bs[bk][bn] = b4;
        __syncthreads();
#pragma unroll
        for (int kk = 0; kk < 8; kk++) {
            float a[8], b[8];
#pragma unroll
            for (int x = 0; x < 8; x++) { a[x] = As[kk][tr * 8 + x]; b[x] = Bs[kk][tc * 8 + x]; }
#pragma unroll
            for (int y = 0; y < 8; y++)
#pragma unroll
                for (int x = 0; x < 8; x++) acc[y][x] = fmaf(a[y], b[x], acc[y][x]);
        }
        __syncthreads();
    }
#pragma unroll
    for (int y = 0; y < 8; y++) {
        int m = row0 + tr * 8 + y;
#pragma unroll
        for (int x = 0; x < 8; x++) {
            int n = col0 + tc * 8 + x;
            float val = acc[y][x];
            if (bias) val += bias[n];
            C[(size_t)m * ldc + n] = val;
        }
    }
}

// ---------------- RoPE + layout split -----------------
__global__ void rope_kernel(const float* __restrict__ cosp, const float* __restrict__ sinp) {
    int idx = blockIdx.x * blockDim.x + threadIdx.x;
    if (idx >= SQ * QKV_N) return;
    int s = idx / QKV_N, c = idx - s * QKV_N;
    float val = g_qkv[idx];
    if (c < 2048) {                       // q
        int h = c >> 7, d = c & 127;
        float cs = cosp[s * HDIM + d], sn = sinp[s * HDIM + d];
        float other = (d < 64) ? -g_qkv[idx + 64] : g_qkv[idx - 64];
        g_q[((size_t)h * SQ + s) * HDIM + d] = val * cs + other * sn;
    } else if (c < 2560) {                // k
        int cc = c - 2048, h = cc >> 7, d = cc & 127;
        float cs = cosp[s * HDIM + d], sn = sinp[s * HDIM + d];
        float other = (d < 64) ? -g_qkv[idx + 64] : g_qkv[idx - 64];
        g_k[((size_t)h * SQ + s) * HDIM + d] = val * cs + other * sn;
    } else {                              // v
        int cc = c - 2560, h = cc >> 7, d = cc & 127;
        g_v[((size_t)h * SQ + s) * HDIM + d] = val;
    }
}

// ---------------- scores = scale * q @ k^T, causal (only j<=i written) ------
__global__ __launch_bounds__(256) void qk_kernel() {
    if (blockIdx.x > blockIdx.y) return;   // fully above diagonal
    int h = blockIdx.z;
    int i0 = blockIdx.y * 128, j0 = blockIdx.x * 128;
    const float* Q  = g_q + (size_t)h * SQ * HDIM;
    const float* Kp = g_k + (size_t)(h >> 2) * SQ * HDIM;
    __shared__ float Qs[8][128];
    __shared__ float Ks[8][128];
    int tid = threadIdx.x;
    int tr = tid >> 4, tc = tid & 15;
    float acc[8][8];
#pragma unroll
    for (int y = 0; y < 8; y++)
#pragma unroll
        for (int x = 0; x < 8; x++) acc[y][x] = 0.f;

    int am = (tid * 4) >> 3, ak = (tid * 4) & 7;
    for (int d0 = 0; d0 < HDIM; d0 += 8) {
        float4 qa = *(const float4*)&Q[(size_t)(i0 + am) * HDIM + d0 + ak];
        float4 ka = *(const float4*)&Kp[(size_t)(j0 + am) * HDIM + d0 + ak];
        Qs[ak + 0][am] = qa.x; Qs[ak + 1][am] = qa.y; Qs[ak + 2][am] = qa.z; Qs[ak + 3][am] = qa.w;
        Ks[ak + 0][am] = ka.x; Ks[ak + 1][am] = ka.y; Ks[ak + 2][am] = ka.z; Ks[ak + 3][am] = ka.w;
        __syncthreads();
#pragma unroll
        for (int kk = 0; kk < 8; kk++) {
            float a[8], b[8];
#pragma unroll
            for (int x = 0; x < 8; x++) { a[x] = Qs[kk][tr * 8 + x]; b[x] = Ks[kk][tc * 8 + x]; }
#pragma unroll
            for (int y = 0; y < 8; y++)
#pragma unroll
                for (int x = 0; x < 8; x++) acc[y][x] = fmaf(a[y], b[x], acc[y][x]);
        }
        __syncthreads();
    }
    const float scale = 0.08838834764831845f;  // 1/sqrt(128)
    float* E = g_e + (size_t)h * SQ * SQ;
#pragma unroll
    for (int y = 0; y < 8; y++) {
        int i = i0 + tr * 8 + y;
#pragma unroll
        for (int x = 0; x < 8; x++) {
            int j = j0 + tc * 8 + x;
            if (j <= i) E[(size_t)i * SQ + j] = acc[y][x] * scale;
        }
    }
}

// ---------------- per-row: max, e = exp(s-m) in place, 1/sum ----------------
__global__ void rowexp_kernel() {
    int i = blockIdx.x, h = blockIdx.y, tid = threadIdx.x;   // 128 threads
    float* row = g_e + ((size_t)h * SQ + i) * SQ;
    int n = i + 1;
    float m = -1e30f;
    for (int j = tid; j < n; j += 128) m = fmaxf(m, row[j]);
    __shared__ float red[4];
    m = warp_red_max(m);
    if ((tid & 31) == 0) red[tid >> 5] = m;
    __syncthreads();
    m = fmaxf(fmaxf(red[0], red[1]), fmaxf(red[2], red[3]));
    float ssum = 0.f;
    for (int j = tid; j < n; j += 128) { float e = __expf(row[j] - m); row[j] = e; ssum += e; }
    __syncthreads();
    ssum = warp_red_sum(ssum);
    if ((tid & 31) == 0) red[tid >> 5] = ssum;
    __syncthreads();
    if (tid == 0) g_invrsum[h * SQ + i] = 1.0f / (red[0] + red[1] + red[2] + red[3]);
}

// ---------------- column sums of the full-causal softmax --------------------
__global__ void colsum_kernel() {
    int h = blockIdx.y;
    int j = blockIdx.x * 256 + threadIdx.x;
    int istart = blockIdx.x * 256;               // min j in block
    const float* E = g_e + (size_t)h * SQ * SQ;
    float acc = 0.f;
    for (int i = istart; i < SQ; i++) {
        if (i >= j) acc += E[(size_t)i * SQ + j] * g_invrsum[h * SQ + i];
    }
    g_colsum[h * SQ + j] = acc;
}

// ---------------- per-head top-204 threshold via bitonic sort ---------------
__global__ __launch_bounds__(1024) void topk_kernel() {
    __shared__ float sv[2048];
    int h = blockIdx.x, tid = threadIdx.x;       // 1024 threads
    sv[tid] = g_colsum[h * SQ + tid];
    sv[tid + 1024] = g_colsum[h * SQ + tid + 1024];
    __syncthreads();
    for (int k = 2; k <= 2048; k <<= 1) {
        for (int j = k >> 1; j > 0; j >>= 1) {
#pragma unroll 2
            for (int base = 0; base < 2048; base += 1024) {
                int i = base + tid;
                int l = i ^ j;
                if (l > i) {
                    float a = sv[i], b = sv[l];
                    bool up = ((i & k) == 0);
                    if ((a > b) == up) { sv[i] = b; sv[l] = a; }
                }
            }
            __syncthreads();
        }
    }
    float thr = sv[2048 - HEAVY_K];              // 204th largest
    g_heavy[h * SQ + tid]        = (g_colsum[h * SQ + tid]        >= thr) ? 1 : 0;
    g_heavy[h * SQ + tid + 1024] = (g_colsum[h * SQ + tid + 1024] >= thr) ? 1 : 0;
}

// ---------------- masked row sums (second softmax denominator) --------------
__global__ void rowsum2_kernel() {
    int i = blockIdx.x, h = blockIdx.y, tid = threadIdx.x;   // 128 threads
    const float* row = g_e + ((size_t)h * SQ + i) * SQ;
    const unsigned char* hv = g_heavy + h * SQ;
    float s = 0.f;
    for (int j = tid; j <= i; j += 128) {
        if (hv[j] || (i - j) <= RECENT_W) s += row[j];
    }
    __shared__ float red[4];
    s = warp_red_sum(s);
    if ((tid & 31) == 0) red[tid >> 5] = s;
    __syncthreads();
    if (tid == 0) g_invrsum2[h * SQ + i] = 1.0f / (red[0] + red[1] + red[2] + red[3]);
}

// ---------------- out = P_masked @ V  (P generated on the fly) --------------
__global__ __launch_bounds__(256) void av_kernel() {
    int h = blockIdx.y;
    int q0 = blockIdx.x * 128;
    const float* E = g_e + (size_t)h * SQ * SQ;
    const float* V = g_v + (size_t)(h >> 2) * SQ * HDIM;
    const unsigned char* hv = g_heavy + h * SQ;
    __shared__ float Ps[8][128];
    __shared__ float Vs[8][128];
    __shared__ float sinv[128];
    int tid = threadIdx.x;
    if (tid < 128) sinv[tid] = g_invrsum2[h * SQ + q0 + tid];
    __syncthreads();
    int tr = tid >> 4, tc = tid & 15;
    float acc[8][8];
#pragma unroll
    for (int y = 0; y < 8; y++)
#pragma unroll
        for (int x = 0; x < 8; x++) acc[y][x] = 0.f;

    int pq = (tid * 4) >> 3, pj = (tid * 4) & 7;
    int vk = (tid * 4) >> 7, vd = (tid * 4) & 127;
    int jend = q0 + 128;                   // causal: j <= q < q0+128
    for (int j0 = 0; j0 < jend; j0 += 8) {
        int qg = q0 + pq;
        float inv = sinv[pq];
#pragma unroll
        for (int t = 0; t < 4; t++) {
            int jg = j0 + pj + t;
            float p = 0.f;
            if (jg <= qg && (hv[jg] || (qg - jg) <= RECENT_W))
                p = E[(size_t)qg * SQ + jg] * inv;
            Ps[pj + t][pq] = p;
        }
        float4 v4 = *(const float4*)&V[(size_t)(j0 + vk) * HDIM + vd];
        *(float4*)&Vs[vk][vd] = v4;
        __syncthreads();
#pragma unroll
        for (int kk = 0; kk < 8; kk++) {
            float a[8], b[8];
#pragma unroll
            for (int x = 0; x < 8; x++) { a[x] = Ps[kk][tr * 8 + x]; b[x] = Vs[kk][tc * 8 + x]; }
#pragma unroll
            for (int y = 0; y < 8; y++)
#pragma unroll
                for (int x = 0; x < 8; x++) acc[y][x] = fmaf(a[y], b[x], acc[y][x]);
        }
        __syncthreads();
    }
#pragma unroll
    for (int y = 0; y < 8; y++) {
        int qg = q0 + tr * 8 + y;
#pragma unroll
        for (int x = 0; x < 8; x++) {
            int d = tc * 8 + x;
            g_attnout[(size_t)qg * HIDN + h * HDIM + d] = acc[y][x];
        }
    }
}

// ---------------- launch ----------------
extern "C" void kernel_launch(void* const* d_in, const int* in_sizes, int n_in,
                              void* d_out, int out_size) {
    (void)in_sizes; (void)n_in; (void)out_size;
    const float* hidden = (const float*)d_in[0];
    const float* cosp   = (const float*)d_in[1];
    const float* sinp   = (const float*)d_in[2];
    // d_in[3] attention_mask: causal, reproduced analytically
    const float* Wq = (const float*)d_in[4];
    const float* bq = (const float*)d_in[5];
    const float* Wk = (const float*)d_in[6];
    const float* bk = (const float*)d_in[7];
    const float* Wv = (const float*)d_in[8];
    const float* bv = (const float*)d_in[9];
    const float* Wo = (const float*)d_in[10];
    float* out = (float*)d_out;

    void* p;
    cudaGetSymbolAddress(&p, g_qkv);     float* qkv     = (float*)p;
    cudaGetSymbolAddress(&p, g_attnout); float* attnout = (float*)p;

    // QKV projections (+bias)
    gemm_kernel<<<dim3(16, 16), 256>>>(hidden, HIDN, Wq, 2048, bq, qkv,        QKV_N, HIDN);
    gemm_kernel<<<dim3(4, 16),  256>>>(hidden, HIDN, Wk,  512, bk, qkv + 2048, QKV_N, HIDN);
    gemm_kernel<<<dim3(4, 16),  256>>>(hidden, HIDN, Wv,  512, bv, qkv + 2560, QKV_N, HIDN);

    rope_kernel<<<(SQ * QKV_N + 255) / 256, 256>>>(cosp, sinp);

    qk_kernel<<<dim3(16, 16, NHEAD), 256>>>();
    rowexp_kernel<<<dim3(SQ, NHEAD), 128>>>();
    colsum_kernel<<<dim3(8, NHEAD), 256>>>();
    topk_kernel<<<NHEAD, 1024>>>();
    rowsum2_kernel<<<dim3(SQ, NHEAD), 128>>>();
    av_kernel<<<dim3(16, NHEAD), 256>>>();

    // output projection
    gemm_kernel<<<dim3(16, 16), 256>>>(attnout, HIDN, Wo, HIDN, (const float*)nullptr, out, HIDN, HIDN);
}

// round 11
// speedup vs baseline: 1.8929x; 1.8929x over previous
#include <cuda_runtime.h>
#include <cuda_bf16.h>
#include <cstdint>
#include <cstddef>

#define SQ 2048
#define HIDN 2048
#define NHEAD 16
#define NKVH 4
#define HDIM 128
#define QKV_N 3072
#define RECENT_W 204
#define HEAVY_K 204

typedef __nv_bfloat16 bf;
typedef unsigned int u32;

// ---------------- device globals (no allocations allowed) -------------------
__device__ __align__(16) float g_qkv[SQ * QKV_N];
__device__ __align__(16) bf g_hid_h[SQ * HIDN];
__device__ __align__(16) bf g_hid_l[SQ * HIDN];
__device__ __align__(16) bf g_wT_h[(size_t)QKV_N * HIDN];
__device__ __align__(16) bf g_wT_l[(size_t)QKV_N * HIDN];
__device__ __align__(16) bf g_woT_h[(size_t)HIDN * HIDN];
__device__ __align__(16) bf g_woT_l[(size_t)HIDN * HIDN];
__device__ __align__(16) bf g_q_h[NHEAD * SQ * HDIM];
__device__ __align__(16) bf g_q_l[NHEAD * SQ * HDIM];
__device__ __align__(16) bf g_k_h[NKVH * SQ * HDIM];
__device__ __align__(16) bf g_k_l[NKVH * SQ * HDIM];
__device__ __align__(16) float g_v[NKVH * SQ * HDIM];
__device__ __align__(16) bf g_vT_h[NKVH * HDIM * SQ];
__device__ __align__(16) bf g_vT_l[NKVH * HDIM * SQ];
__device__ __align__(16) float g_e[(size_t)NHEAD * SQ * SQ];
__device__ __align__(16) bf g_p_h[(size_t)NHEAD * SQ * SQ];
__device__ __align__(16) bf g_p_l[(size_t)NHEAD * SQ * SQ];
__device__ __align__(16) bf g_ao_h[SQ * HIDN];
__device__ __align__(16) bf g_ao_l[SQ * HIDN];
__device__ float g_invrsum[NHEAD * SQ];
__device__ float g_colsum[NHEAD * SQ];
__device__ float g_invrsum2[NHEAD * SQ];
__device__ unsigned char g_heavy[NHEAD * SQ];

// ---------------- small helpers ----------------
static __device__ __forceinline__ void split2(float x, bf& h, bf& l) {
    h = __float2bfloat16_rn(x);
    l = __float2bfloat16_rn(x - __bfloat162float(h));
}
static __device__ __forceinline__ u32 packbf(bf a, bf b) {
    return (u32)__bfloat16_as_ushort(a) | ((u32)__bfloat16_as_ushort(b) << 16);
}
static __device__ __forceinline__ float warp_red_max(float v) {
#pragma unroll
    for (int o = 16; o > 0; o >>= 1) v = fmaxf(v, __shfl_xor_sync(0xffffffffu, v, o));
    return v;
}
static __device__ __forceinline__ float warp_red_sum(float v) {
#pragma unroll
    for (int o = 16; o > 0; o >>= 1) v += __shfl_xor_sync(0xffffffffu, v, o);
    return v;
}

// ---------------- mma.sync m16n8k16 bf16 (baseline PTX, sm_80+) -----------
static __device__ __forceinline__ void mma_tile(float* d, const u32* a, u32 b0, u32 b1) {
    asm volatile(
        "mma.sync.aligned.m16n8k16.row.col.f32.bf16.bf16.f32 "
        "{%0,%1,%2,%3}, {%4,%5,%6,%7}, {%8,%9}, {%0,%1,%2,%3};"
        : "+f"(d[0]), "+f"(d[1]), "+f"(d[2]), "+f"(d[3])
        : "r"(a[0]), "r"(a[1]), "r"(a[2]), "r"(a[3]), "r"(b0), "r"(b1));
}

// ---------------- bf16x3 GEMM mainloop ------------------------------------
// Block tile 128x128, K-chunk 32, double-buffered SMEM (padded stride 40),
// 8 warps in 4(M)x2(N) layout, warp tile 32x64.
// A: M rows, K-major (hi/lo). B: N rows, K-major (hi/lo). acc += A*B^T 3-pass.
#define TP 40
#define TILEE (128 * TP)             // elements per tile
#define STAGEE (4 * TILEE)
#define SMEMB (2 * STAGEE * 2)       // bytes: 2 stages * 4 tiles * 10240B = 81920

static __device__ __forceinline__ void mainloop(
    bf* smem,
    const bf* __restrict__ Ah, const bf* __restrict__ Al, int lda,
    const bf* __restrict__ Bh, const bf* __restrict__ Bl, int ldb,
    int nchunk, int tid, float acc[2][8][4])
{
    int r = tid >> 1, halfe = (tid & 1) << 4;
    int lane = tid & 31, wid = tid >> 5;
    int g = lane >> 2, tig = lane & 3;
    int wm = wid & 3, wn = wid >> 2;

    // prologue: chunk 0 -> stage 0
    {
        const uint4* s0 = (const uint4*)(Ah + (size_t)r * lda + halfe);
        const uint4* s1 = (const uint4*)(Al + (size_t)r * lda + halfe);
        const uint4* s2 = (const uint4*)(Bh + (size_t)r * ldb + halfe);
        const uint4* s3 = (const uint4*)(Bl + (size_t)r * ldb + halfe);
        uint4* d = (uint4*)(smem + r * TP + halfe);
        d[0] = s0[0]; d[1] = s0[1];
        d = (uint4*)(smem + TILEE + r * TP + halfe);
        d[0] = s1[0]; d[1] = s1[1];
        d = (uint4*)(smem + 2 * TILEE + r * TP + halfe);
        d[0] = s2[0]; d[1] = s2[1];
        d = (uint4*)(smem + 3 * TILEE + r * TP + halfe);
        d[0] = s3[0]; d[1] = s3[1];
    }
    __syncthreads();

    uint4 st[4][2];
    for (int c = 0; c < nchunk; c++) {
        if (c + 1 < nchunk) {
            int k0 = (c + 1) << 5;
            const uint4* s0 = (const uint4*)(Ah + (size_t)r * lda + k0 + halfe);
            const uint4* s1 = (const uint4*)(Al + (size_t)r * lda + k0 + halfe);
            const uint4* s2 = (const uint4*)(Bh + (size_t)r * ldb + k0 + halfe);
            const uint4* s3 = (const uint4*)(Bl + (size_t)r * ldb + k0 + halfe);
            st[0][0] = s0[0]; st[0][1] = s0[1];
            st[1][0] = s1[0]; st[1][1] = s1[1];
            st[2][0] = s2[0]; st[2][1] = s2[1];
            st[3][0] = s3[0]; st[3][1] = s3[1];
        }
        const bf* buf = smem + (c & 1) * STAGEE;
        const bf* As_h = buf;
        const bf* As_l = buf + TILEE;
        const bf* Bs_h = buf + 2 * TILEE;
        const bf* Bs_l = buf + 3 * TILEE;
#pragma unroll
        for (int ks = 0; ks < 32; ks += 16) {
            u32 ah[2][4], al[2][4];
#pragma unroll
            for (int mt = 0; mt < 2; mt++) {
                int rb = wm * 32 + mt * 16;
                ah[mt][0] = *(const u32*)&As_h[(rb + g) * TP + ks + 2 * tig];
                ah[mt][1] = *(const u32*)&As_h[(rb + g + 8) * TP + ks + 2 * tig];
                ah[mt][2] = *(const u32*)&As_h[(rb + g) * TP + ks + 2 * tig + 8];
                ah[mt][3] = *(const u32*)&As_h[(rb + g + 8) * TP + ks + 2 * tig + 8];
                al[mt][0] = *(const u32*)&As_l[(rb + g) * TP + ks + 2 * tig];
                al[mt][1] = *(const u32*)&As_l[(rb + g + 8) * TP + ks + 2 * tig];
                al[mt][2] = *(const u32*)&As_l[(rb + g) * TP + ks + 2 * tig + 8];
                al[mt][3] = *(const u32*)&As_l[(rb + g + 8) * TP + ks + 2 * tig + 8];
            }
#pragma unroll
            for (int nb = 0; nb < 8; nb++) {
                int nr = wn * 64 + nb * 8 + g;
                u32 bh0 = *(const u32*)&Bs_h[nr * TP + ks + 2 * tig];
                u32 bh1 = *(const u32*)&Bs_h[nr * TP + ks + 2 * tig + 8];
                u32 bl0 = *(const u32*)&Bs_l[nr * TP + ks + 2 * tig];
                u32 bl1 = *(const u32*)&Bs_l[nr * TP + ks + 2 * tig + 8];
#pragma unroll
                for (int mt = 0; mt < 2; mt++) {
                    mma_tile(acc[mt][nb], ah[mt], bh0, bh1);
                    mma_tile(acc[mt][nb], al[mt], bh0, bh1);
                    mma_tile(acc[mt][nb], ah[mt], bl0, bl1);
                }
            }
        }
        if (c + 1 < nchunk) {
            bf* nbuf = smem + ((c + 1) & 1) * STAGEE;
            uint4* d = (uint4*)(nbuf + r * TP + halfe);
            d[0] = st[0][0]; d[1] = st[0][1];
            d = (uint4*)(nbuf + TILEE + r * TP + halfe);
            d[0] = st[1][0]; d[1] = st[1][1];
            d = (uint4*)(nbuf + 2 * TILEE + r * TP + halfe);
            d[0] = st[2][0]; d[1] = st[2][1];
            d = (uint4*)(nbuf + 3 * TILEE + r * TP + halfe);
            d[0] = st[3][0]; d[1] = st[3][1];
        }
        __syncthreads();
    }
}

// ---------------- GEMM kernels ----------------
__global__ __launch_bounds__(256) void mm_lin(
    const bf* __restrict__ Ah, const bf* __restrict__ Al,
    const bf* __restrict__ Bh, const bf* __restrict__ Bl,
    int K, float* __restrict__ C, int ldc, int coloff, const float* __restrict__ bias)
{
    extern __shared__ bf smem[];
    int tid = threadIdx.x;
    int row0 = blockIdx.y << 7, colb = blockIdx.x << 7;
    float acc[2][8][4];
#pragma unroll
    for (int a = 0; a < 2; a++)
#pragma unroll
        for (int b = 0; b < 8; b++)
#pragma unroll
            for (int c = 0; c < 4; c++) acc[a][b][c] = 0.f;

    mainloop(smem, Ah + (size_t)row0 * K, Al + (size_t)row0 * K, K,
             Bh + (size_t)colb * K, Bl + (size_t)colb * K, K, K >> 5, tid, acc);

    int lane = tid & 31, wid = tid >> 5;
    int g = lane >> 2, tig = lane & 3, wm = wid & 3, wn = wid >> 2;
#pragma unroll
    for (int mt = 0; mt < 2; mt++)
#pragma unroll
        for (int nb = 0; nb < 8; nb++) {
            int gr = row0 + wm * 32 + mt * 16 + g;
            int gc = colb + wn * 64 + nb * 8 + 2 * tig;
            float b0 = 0.f, b1 = 0.f;
            if (bias) { b0 = bias[gc]; b1 = bias[gc + 1]; }
            float* p0 = &C[(size_t)gr * ldc + coloff + gc];
            float* p1 = &C[(size_t)(gr + 8) * ldc + coloff + gc];
            p0[0] = acc[mt][nb][0] + b0; p0[1] = acc[mt][nb][1] + b1;
            p1[0] = acc[mt][nb][2] + b0; p1[1] = acc[mt][nb][3] + b1;
        }
}

__global__ __launch_bounds__(256) void mm_qk() {
    int jt = blockIdx.x, it = blockIdx.y, h = blockIdx.z;
    if (jt > it) return;
    extern __shared__ bf smem[];
    int tid = threadIdx.x;
    int i0 = it << 7, j0 = jt << 7;
    size_t qo = ((size_t)h * SQ + i0) * HDIM;
    size_t ko = ((size_t)(h >> 2) * SQ + j0) * HDIM;
    float acc[2][8][4];
#pragma unroll
    for (int a = 0; a < 2; a++)
#pragma unroll
        for (int b = 0; b < 8; b++)
#pragma unroll
            for (int c = 0; c < 4; c++) acc[a][b][c] = 0.f;

    mainloop(smem, g_q_h + qo, g_q_l + qo, HDIM, g_k_h + ko, g_k_l + ko, HDIM, 4, tid, acc);

    int lane = tid & 31, wid = tid >> 5;
    int g = lane >> 2, tig = lane & 3, wm = wid & 3, wn = wid >> 2;
    const float scale = 0.08838834764831845f;
    float* E = g_e + (size_t)h * SQ * SQ;
#pragma unroll
    for (int mt = 0; mt < 2; mt++)
#pragma unroll
        for (int nb = 0; nb < 8; nb++) {
            int gi = i0 + wm * 32 + mt * 16 + g;
            int gj = j0 + wn * 64 + nb * 8 + 2 * tig;
            if (gj <= gi)     E[(size_t)gi * SQ + gj]     = acc[mt][nb][0] * scale;
            if (gj + 1 <= gi) E[(size_t)gi * SQ + gj + 1] = acc[mt][nb][1] * scale;
            int gi8 = gi + 8;
            if (gj <= gi8)     E[(size_t)gi8 * SQ + gj]     = acc[mt][nb][2] * scale;
            if (gj + 1 <= gi8) E[(size_t)gi8 * SQ + gj + 1] = acc[mt][nb][3] * scale;
        }
}

__global__ __launch_bounds__(256) void mm_av() {
    int qt = blockIdx.x, h = blockIdx.y;
    extern __shared__ bf smem[];
    int tid = threadIdx.x;
    int q0 = qt << 7;
    size_t po = ((size_t)h * SQ + q0) * SQ;
    size_t vo = (size_t)(h >> 2) * HDIM * SQ;
    float acc[2][8][4];
#pragma unroll
    for (int a = 0; a < 2; a++)
#pragma unroll
        for (int b = 0; b < 8; b++)
#pragma unroll
            for (int c = 0; c < 4; c++) acc[a][b][c] = 0.f;

    mainloop(smem, g_p_h + po, g_p_l + po, SQ, g_vT_h + vo, g_vT_l + vo, SQ,
             4 * (qt + 1), tid, acc);

    int lane = tid & 31, wid = tid >> 5;
    int g = lane >> 2, tig = lane & 3, wm = wid & 3, wn = wid >> 2;
#pragma unroll
    for (int mt = 0; mt < 2; mt++)
#pragma unroll
        for (int nb = 0; nb < 8; nb++) {
            int gq = q0 + wm * 32 + mt * 16 + g;
            int gc = wn * 64 + nb * 8 + 2 * tig;
            bf h0, l0, h1, l1;
            split2(acc[mt][nb][0], h0, l0); split2(acc[mt][nb][1], h1, l1);
            size_t o = (size_t)gq * HIDN + (h << 7) + gc;
            *(u32*)(g_ao_h + o) = packbf(h0, h1);
            *(u32*)(g_ao_l + o) = packbf(l0, l1);
            split2(acc[mt][nb][2], h0, l0); split2(acc[mt][nb][3], h1, l1);
            o = (size_t)(gq + 8) * HIDN + (h << 7) + gc;
            *(u32*)(g_ao_h + o) = packbf(h0, h1);
            *(u32*)(g_ao_l + o) = packbf(l0, l1);
        }
}

// ---------------- prep kernels ----------------
__global__ void split_rm(const float* __restrict__ src, bf* __restrict__ h,
                         bf* __restrict__ l, int n) {
    int i = blockIdx.x * blockDim.x + threadIdx.x;
    if (i < n) { bf a, b; split2(src[i], a, b); h[i] = a; l[i] = b; }
}

// W [K x N] fp32 -> dst [N x K] bf16 hi/lo (tiled transpose)
__global__ void split_tr(const float* __restrict__ src, int N,
                         bf* __restrict__ dh, bf* __restrict__ dl, int K) {
    __shared__ float t[32][33];
    int k0 = blockIdx.x << 5, n0 = blockIdx.y << 5;
    int tx = threadIdx.x, ty = threadIdx.y;
#pragma unroll
    for (int r = 0; r < 4; r++)
        t[ty + r * 8][tx] = src[(size_t)(k0 + ty + r * 8) * N + n0 + tx];
    __syncthreads();
#pragma unroll
    for (int r = 0; r < 4; r++) {
        int k = k0 + tx, n = n0 + ty + r * 8;
        bf a, b; split2(t[tx][ty + r * 8], a, b);
        dh[(size_t)n * K + k] = a;
        dl[(size_t)n * K + k] = b;
    }
}

__global__ void rope_kernel(const float* __restrict__ cosp, const float* __restrict__ sinp) {
    int idx = blockIdx.x * blockDim.x + threadIdx.x;
    if (idx >= SQ * QKV_N) return;
    int s = idx / QKV_N, c = idx - s * QKV_N;
    float val = g_qkv[idx];
    if (c < 2048) {
        int h = c >> 7, d = c & 127;
        float cs = cosp[s * HDIM + d], sn = sinp[s * HDIM + d];
        float other = (d < 64) ? -g_qkv[idx + 64] : g_qkv[idx - 64];
        float r = val * cs + other * sn;
        bf a, b; split2(r, a, b);
        size_t o = ((size_t)h * SQ + s) * HDIM + d;
        g_q_h[o] = a; g_q_l[o] = b;
    } else if (c < 2560) {
        int cc = c - 2048, h = cc >> 7, d = cc & 127;
        float cs = cosp[s * HDIM + d], sn = sinp[s * HDIM + d];
        float other = (d < 64) ? -g_qkv[idx + 64] : g_qkv[idx - 64];
        float r = val * cs + other * sn;
        bf a, b; split2(r, a, b);
        size_t o = ((size_t)h * SQ + s) * HDIM + d;
        g_k_h[o] = a; g_k_l[o] = b;
    } else {
        int cc = c - 2560, h = cc >> 7, d = cc & 127;
        g_v[((size_t)h * SQ + s) * HDIM + d] = val;
    }
}

// v [h][s][d] fp32 -> vT [h][d][s] bf16 hi/lo
__global__ void vtsplit_kernel() {
    __shared__ float t[32][33];
    int h = blockIdx.z;
    int s0 = blockIdx.x << 5, d0 = blockIdx.y << 5;
    int tx = threadIdx.x, ty = threadIdx.y;
    const float* V = g_v + (size_t)h * SQ * HDIM;
#pragma unroll
    for (int k = 0; k < 4; k++)
        t[ty + k * 8][tx] = V[(size_t)(s0 + ty + k * 8) * HDIM + d0 + tx];
    __syncthreads();
    bf* oh = g_vT_h + (size_t)h * HDIM * SQ;
    bf* ol = g_vT_l + (size_t)h * HDIM * SQ;
#pragma unroll
    for (int k = 0; k < 4; k++) {
        int d = d0 + ty + k * 8, s = s0 + tx;
        bf a, b; split2(t[tx][ty + k * 8], a, b);
        oh[(size_t)d * SQ + s] = a;
        ol[(size_t)d * SQ + s] = b;
    }
}

// ---------------- softmax / H2O passes ---------------------
__global__ void rowexp_kernel() {
    int i = blockIdx.x, h = blockIdx.y, tid = threadIdx.x;
    float* row = g_e + ((size_t)h * SQ + i) * SQ;
    int n = i + 1;
    float m = -1e30f;
    for (int j = tid; j < n; j += 128) m = fmaxf(m, row[j]);
    __shared__ float red[4];
    m = warp_red_max(m);
    if ((tid & 31) == 0) red[tid >> 5] = m;
    __syncthreads();
    m = fmaxf(fmaxf(red[0], red[1]), fmaxf(red[2], red[3]));
    float ssum = 0.f;
    for (int j = tid; j < n; j += 128) { float e = __expf(row[j] - m); row[j] = e; ssum += e; }
    __syncthreads();
    ssum = warp_red_sum(ssum);
    if ((tid & 31) == 0) red[tid >> 5] = ssum;
    __syncthreads();
    if (tid == 0) g_invrsum[h * SQ + i] = 1.0f / (red[0] + red[1] + red[2] + red[3]);
}

__global__ void colsum_kernel() {
    int h = blockIdx.y;
    int j = blockIdx.x * 256 + threadIdx.x;
    int istart = blockIdx.x * 256;
    const float* E = g_e + (size_t)h * SQ * SQ;
    float acc = 0.f;
    for (int i = istart; i < SQ; i++)
        if (i >= j) acc += E[(size_t)i * SQ + j] * g_invrsum[h * SQ + i];
    g_colsum[h * SQ + j] = acc;
}

__global__ __launch_bounds__(1024) void topk_kernel() {
    __shared__ float sv[2048];
    int h = blockIdx.x, tid = threadIdx.x;
    sv[tid] = g_colsum[h * SQ + tid];
    sv[tid + 1024] = g_colsum[h * SQ + tid + 1024];
    __syncthreads();
    for (int k = 2; k <= 2048; k <<= 1) {
        for (int j = k >> 1; j > 0; j >>= 1) {
#pragma unroll 2
            for (int base = 0; base < 2048; base += 1024) {
                int i = base + tid;
                int l = i ^ j;
                if (l > i) {
                    float a = sv[i], b = sv[l];
                    bool up = ((i & k) == 0);
                    if ((a > b) == up) { sv[i] = b; sv[l] = a; }
                }
            }
            __syncthreads();
        }
    }
    float thr = sv[2048 - HEAVY_K];
    g_heavy[h * SQ + tid]        = (g_colsum[h * SQ + tid]        >= thr) ? 1 : 0;
    g_heavy[h * SQ + tid + 1024] = (g_colsum[h * SQ + tid + 1024] >= thr) ? 1 : 0;
}

__global__ void rowsum2_kernel() {
    int i = blockIdx.x, h = blockIdx.y, tid = threadIdx.x;
    const float* row = g_e + ((size_t)h * SQ + i) * SQ;
    const unsigned char* hv = g_heavy + h * SQ;
    float s = 0.f;
    for (int j = tid; j <= i; j += 128)
        if (hv[j] || (i - j) <= RECENT_W) s += row[j];
    __shared__ float red[4];
    s = warp_red_sum(s);
    if ((tid & 31) == 0) red[tid >> 5] = s;
    __syncthreads();
    if (tid == 0) g_invrsum2[h * SQ + i] = 1.0f / (red[0] + red[1] + red[2] + red[3]);
}

// masked P = e*inv (zeros elsewhere), split to bf16 hi/lo up to tile boundary
__global__ void psplit_kernel() {
    int q = blockIdx.x, h = blockIdx.y, tid = threadIdx.x;
    const float* row = g_e + ((size_t)h * SQ + q) * SQ;
    const unsigned char* hv = g_heavy + h * SQ;
    float inv = g_invrsum2[h * SQ + q];
    int jmax = ((q >> 7) + 1) << 7;
    bf* ph = g_p_h + ((size_t)h * SQ + q) * SQ;
    bf* pl = g_p_l + ((size_t)h * SQ + q) * SQ;
    for (int j = tid; j < jmax; j += 256) {
        float p = 0.f;
        if (j <= q && (hv[j] || (q - j) <= RECENT_W)) p = row[j] * inv;
        bf a, b; split2(p, a, b);
        ph[j] = a; pl[j] = b;
    }
}

// ---------------- launch ----------------
extern "C" void kernel_launch(void* const* d_in, const int* in_sizes, int n_in,
                              void* d_out, int out_size) {
    (void)in_sizes; (void)n_in; (void)out_size;
    const float* hidden = (const float*)d_in[0];
    const float* cosp   = (const float*)d_in[1];
    const float* sinp   = (const float*)d_in[2];
    const float* Wq = (const float*)d_in[4];
    const float* bq = (const float*)d_in[5];
    const float* Wk = (const float*)d_in[6];
    const float* bk = (const float*)d_in[7];
    const float* Wv = (const float*)d_in[8];
    const float* bv = (const float*)d_in[9];
    const float* Wo = (const float*)d_in[10];
    float* out = (float*)d_out;

    cudaFuncSetAttribute(mm_lin, cudaFuncAttributeMaxDynamicSharedMemorySize, SMEMB);
    cudaFuncSetAttribute(mm_qk,  cudaFuncAttributeMaxDynamicSharedMemorySize, SMEMB);
    cudaFuncSetAttribute(mm_av,  cudaFuncAttributeMaxDynamicSharedMemorySize, SMEMB);

    void* p;
    cudaGetSymbolAddress(&p, g_qkv);   float* qkv  = (float*)p;
    cudaGetSymbolAddress(&p, g_hid_h); bf* hid_h = (bf*)p;
    cudaGetSymbolAddress(&p, g_hid_l); bf* hid_l = (bf*)p;
    cudaGetSymbolAddress(&p, g_wT_h);  bf* wT_h  = (bf*)p;
    cudaGetSymbolAddress(&p, g_wT_l);  bf* wT_l  = (bf*)p;
    cudaGetSymbolAddress(&p, g_woT_h); bf* woT_h = (bf*)p;
    cudaGetSymbolAddress(&p, g_woT_l); bf* woT_l = (bf*)p;
    cudaGetSymbolAddress(&p, g_ao_h);  bf* ao_h  = (bf*)p;
    cudaGetSymbolAddress(&p, g_ao_l);  bf* ao_l  = (bf*)p;

    // split inputs / transpose weights to K-major bf16 hi/lo
    split_rm<<<(SQ * HIDN + 1023) / 1024, 1024>>>(hidden, hid_h, hid_l, SQ * HIDN);
    split_tr<<<dim3(64, 64), dim3(32, 8)>>>(Wq, 2048, wT_h, wT_l, HIDN);
    split_tr<<<dim3(64, 16), dim3(32, 8)>>>(Wk, 512, wT_h + (size_t)2048 * HIDN, wT_l + (size_t)2048 * HIDN, HIDN);
    split_tr<<<dim3(64, 16), dim3(32, 8)>>>(Wv, 512, wT_h + (size_t)2560 * HIDN, wT_l + (size_t)2560 * HIDN, HIDN);
    split_tr<<<dim3(64, 64), dim3(32, 8)>>>(Wo, 2048, woT_h, woT_l, HIDN);

    // QKV projections (tensor cores, mma.sync bf16x3)
    mm_lin<<<dim3(16, 16), 256, SMEMB>>>(hid_h, hid_l, wT_h, wT_l, HIDN, qkv, QKV_N, 0, bq);
    mm_lin<<<dim3(4, 16), 256, SMEMB>>>(hid_h, hid_l, wT_h + (size_t)2048 * HIDN, wT_l + (size_t)2048 * HIDN, HIDN, qkv, QKV_N, 2048, bk);
    mm_lin<<<dim3(4, 16), 256, SMEMB>>>(hid_h, hid_l, wT_h + (size_t)2560 * HIDN, wT_l + (size_t)2560 * HIDN, HIDN, qkv, QKV_N, 2560, bv);

    rope_kernel<<<(SQ * QKV_N + 255) / 256, 256>>>(cosp, sinp);
    vtsplit_kernel<<<dim3(64, 4, NKVH), dim3(32, 8)>>>();

    mm_qk<<<dim3(16, 16, NHEAD), 256, SMEMB>>>();
    rowexp_kernel<<<dim3(SQ, NHEAD), 128>>>();
    colsum_kernel<<<dim3(8, NHEAD), 256>>>();
    topk_kernel<<<NHEAD, 1024>>>();
    rowsum2_kernel<<<dim3(SQ, NHEAD), 128>>>();
    psplit_kernel<<<dim3(SQ, NHEAD), 256>>>();
    mm_av<<<dim3(16, NHEAD), 256, SMEMB>>>();

    // output projection
    mm_lin<<<dim3(16, 16), 256, SMEMB>>>(ao_h, ao_l, woT_h, woT_l, HIDN, out, HIDN, 0, (const float*)nullptr);
}

// round 14
// speedup vs baseline: 2.1771x; 1.1501x over previous
#include <cuda_runtime.h>
#include <cuda_bf16.h>
#include <cstdint>
#include <cstddef>

#define SQ 2048
#define HIDN 2048
#define NHEAD 16
#define NKVH 4
#define HDIM 128
#define QKV_N 3072
#define RECENT_W 204
#define HEAVY_K 204

typedef __nv_bfloat16 bf;
typedef unsigned int u32;

// ---------------- device globals (no allocations allowed) -------------------
__device__ __align__(16) float g_qkv[SQ * QKV_N];
__device__ __align__(16) bf g_hid_h[SQ * HIDN];
__device__ __align__(16) bf g_hid_l[SQ * HIDN];
__device__ __align__(16) bf g_wT_h[(size_t)QKV_N * HIDN];
__device__ __align__(16) bf g_wT_l[(size_t)QKV_N * HIDN];
__device__ __align__(16) bf g_woT_h[(size_t)HIDN * HIDN];
__device__ __align__(16) bf g_woT_l[(size_t)HIDN * HIDN];
__device__ __align__(16) bf g_q_h[NHEAD * SQ * HDIM];
__device__ __align__(16) bf g_q_l[NHEAD * SQ * HDIM];
__device__ __align__(16) bf g_k_h[NKVH * SQ * HDIM];
__device__ __align__(16) bf g_k_l[NKVH * SQ * HDIM];
__device__ __align__(16) float g_v[NKVH * SQ * HDIM];
__device__ __align__(16) bf g_vT_h[NKVH * HDIM * SQ];
__device__ __align__(16) bf g_vT_l[NKVH * HDIM * SQ];
__device__ __align__(16) float g_e[(size_t)NHEAD * SQ * SQ];
__device__ __align__(16) bf g_p_h[(size_t)NHEAD * SQ * SQ];
__device__ __align__(16) bf g_p_l[(size_t)NHEAD * SQ * SQ];
__device__ __align__(16) bf g_ao_h[SQ * HIDN];
__device__ __align__(16) bf g_ao_l[SQ * HIDN];
__device__ float g_invrsum[NHEAD * SQ];
__device__ float g_colsum[NHEAD * SQ];
__device__ unsigned char g_heavy[NHEAD * SQ];

// ---------------- small helpers ----------------
static __device__ __forceinline__ void split2(float x, bf& h, bf& l) {
    h = __float2bfloat16_rn(x);
    l = __float2bfloat16_rn(x - __bfloat162float(h));
}
static __device__ __forceinline__ u32 packbf(bf a, bf b) {
    return (u32)__bfloat16_as_ushort(a) | ((u32)__bfloat16_as_ushort(b) << 16);
}
static __device__ __forceinline__ float warp_red_max(float v) {
#pragma unroll
    for (int o = 16; o > 0; o >>= 1) v = fmaxf(v, __shfl_xor_sync(0xffffffffu, v, o));
    return v;
}
static __device__ __forceinline__ float warp_red_sum(float v) {
#pragma unroll
    for (int o = 16; o > 0; o >>= 1) v += __shfl_xor_sync(0xffffffffu, v, o);
    return v;
}
// fast exp for x <= 0: FFMA-pipe polynomial (error ~1.3e-6 rel), no MUFU.
static __device__ __forceinline__ float fexp(float x) {
    float y = x * 1.4426950408889634f;         // log2(e)
    if (y < -126.0f) return 0.0f;
    float f = floorf(y);
    float r = y - f;
    float p = 1.525273380405984e-5f;
    p = fmaf(p, r, 1.5403530393381608e-4f);
    p = fmaf(p, r, 1.3333558146428443e-3f);
    p = fmaf(p, r, 9.618129107628477e-3f);
    p = fmaf(p, r, 5.550410866482158e-2f);
    p = fmaf(p, r, 2.4022650695910072e-1f);
    p = fmaf(p, r, 6.931471805599453e-1f);
    p = fmaf(p, r, 1.0f);
    float sc = __int_as_float(((int)f + 127) << 23);
    return sc * p;
}

// ---------------- mma.sync m16n8k16 bf16 (baseline PTX, sm_80+) -----------
static __device__ __forceinline__ void mma_tile(float* d, const u32* a, u32 b0, u32 b1) {
    asm volatile(
        "mma.sync.aligned.m16n8k16.row.col.f32.bf16.bf16.f32 "
        "{%0,%1,%2,%3}, {%4,%5,%6,%7}, {%8,%9}, {%0,%1,%2,%3};"
        : "+f"(d[0]), "+f"(d[1]), "+f"(d[2]), "+f"(d[3])
        : "r"(a[0]), "r"(a[1]), "r"(a[2]), "r"(a[3]), "r"(b0), "r"(b1));
}
static __device__ __forceinline__ void ldsm_x4(u32* r, u32 addr) {
    asm volatile("ldmatrix.sync.aligned.m8n8.x4.shared.b16 {%0,%1,%2,%3}, [%4];"
        : "=r"(r[0]), "=r"(r[1]), "=r"(r[2]), "=r"(r[3]) : "r"(addr));
}
static __device__ __forceinline__ u32 smem_u32(const void* p) {
    u32 a;
    asm("{ .reg .u64 t; cvta.to.shared.u64 t, %1; cvt.u32.u64 %0, t; }" : "=r"(a) : "l"(p));
    return a;
}

// ---------------- bf16x3 GEMM mainloop ------------------------------------
// Block tile 128x128, K-chunk 32, double-buffered SMEM (padded stride 40),
// 8 warps in 4(M)x2(N) layout, warp tile 32x64, ldmatrix fragment loads.
#define TP 40
#define TILEE (128 * TP)             // elements per tile
#define STAGEE (4 * TILEE)
#define SMEMB (2 * STAGEE * 2)       // bytes

static __device__ __forceinline__ void mainloop(
    bf* smem,
    const bf* __restrict__ Ah, const bf* __restrict__ Al, int lda,
    const bf* __restrict__ Bh, const bf* __restrict__ Bl, int ldb,
    int nchunk, int tid, float acc[2][8][4])
{
    int r = tid >> 1, halfe = (tid & 1) << 4;
    int lane = tid & 31, wid = tid >> 5;
    int wm = wid & 3, wn = wid >> 2;
    u32 sbase = smem_u32(smem);
    // ldmatrix per-lane offsets (bytes)
    u32 aoff = (u32)(((lane & 15) * TP + ((lane >> 4) << 3)) << 1);
    u32 boff = (u32)(((((lane & 7) + ((lane >> 4) << 3)) * TP) + (((lane >> 3) & 1) << 3)) << 1);
    u32 aA0 = sbase + aoff + (u32)((wm * 32 * TP) << 1);
    u32 bB0 = sbase + (u32)((2 * TILEE) << 1) + boff + (u32)((wn * 64 * TP) << 1);

    // prologue: chunk 0 -> stage 0
    {
        const uint4* s0 = (const uint4*)(Ah + (size_t)r * lda + halfe);
        const uint4* s1 = (const uint4*)(Al + (size_t)r * lda + halfe);
        const uint4* s2 = (const uint4*)(Bh + (size_t)r * ldb + halfe);
        const uint4* s3 = (const uint4*)(Bl + (size_t)r * ldb + halfe);
        uint4* d = (uint4*)(smem + r * TP + halfe);
        d[0] = s0[0]; d[1] = s0[1];
        d = (uint4*)(smem + TILEE + r * TP + halfe);
        d[0] = s1[0]; d[1] = s1[1];
        d = (uint4*)(smem + 2 * TILEE + r * TP + halfe);
        d[0] = s2[0]; d[1] = s2[1];
        d = (uint4*)(smem + 3 * TILEE + r * TP + halfe);
        d[0] = s3[0]; d[1] = s3[1];
    }
    __syncthreads();

    uint4 st[4][2];
    for (int c = 0; c < nchunk; c++) {
        if (c + 1 < nchunk) {
            int k0 = (c + 1) << 5;
            const uint4* s0 = (const uint4*)(Ah + (size_t)r * lda + k0 + halfe);
            const uint4* s1 = (const uint4*)(Al + (size_t)r * lda + k0 + halfe);
            const uint4* s2 = (const uint4*)(Bh + (size_t)r * ldb + k0 + halfe);
            const uint4* s3 = (const uint4*)(Bl + (size_t)r * ldb + k0 + halfe);
            st[0][0] = s0[0]; st[0][1] = s0[1];
            st[1][0] = s1[0]; st[1][1] = s1[1];
            st[2][0] = s2[0]; st[2][1] = s2[1];
            st[3][0] = s3[0]; st[3][1] = s3[1];
        }
        u32 stb = (u32)((c & 1) * (STAGEE << 1));
#pragma unroll
        for (int ks = 0; ks < 32; ks += 16) {
            u32 ah[2][4], al[2][4];
#pragma unroll
            for (int mt = 0; mt < 2; mt++) {
                u32 ad = aA0 + stb + (u32)(((mt * 16 * TP) + ks) << 1);
                ldsm_x4(ah[mt], ad);
                ldsm_x4(al[mt], ad + (u32)(TILEE << 1));
            }
#pragma unroll
            for (int nbp = 0; nbp < 4; nbp++) {
                u32 bd = bB0 + stb + (u32)(((nbp * 16 * TP) + ks) << 1);
                u32 bh[4], bl[4];
                ldsm_x4(bh, bd);
                ldsm_x4(bl, bd + (u32)(TILEE << 1));
#pragma unroll
                for (int hh = 0; hh < 2; hh++) {
                    int nb = nbp * 2 + hh;
                    u32 b0h = bh[hh * 2], b1h = bh[hh * 2 + 1];
                    u32 b0l = bl[hh * 2], b1l = bl[hh * 2 + 1];
#pragma unroll
                    for (int mt = 0; mt < 2; mt++) {
                        mma_tile(acc[mt][nb], ah[mt], b0h, b1h);
                        mma_tile(acc[mt][nb], al[mt], b0h, b1h);
                        mma_tile(acc[mt][nb], ah[mt], b0l, b1l);
                    }
                }
            }
        }
        if (c + 1 < nchunk) {
            bf* nbuf = smem + ((c + 1) & 1) * STAGEE;
            uint4* d = (uint4*)(nbuf + r * TP + halfe);
            d[0] = st[0][0]; d[1] = st[0][1];
            d = (uint4*)(nbuf + TILEE + r * TP + halfe);
            d[0] = st[1][0]; d[1] = st[1][1];
            d = (uint4*)(nbuf + 2 * TILEE + r * TP + halfe);
            d[0] = st[2][0]; d[1] = st[2][1];
            d = (uint4*)(nbuf + 3 * TILEE + r * TP + halfe);
            d[0] = st[3][0]; d[1] = st[3][1];
        }
        __syncthreads();
    }
}

// ---------------- GEMM kernels ----------------
__global__ __launch_bounds__(256) void mm_lin(
    const bf* __restrict__ Ah, const bf* __restrict__ Al,
    const bf* __restrict__ Bh, const bf* __restrict__ Bl,
    int K, float* __restrict__ C, int ldc, int coloff, const float* __restrict__ bias)
{
    extern __shared__ bf smem[];
    int tid = threadIdx.x;
    int row0 = blockIdx.y << 7, colb = blockIdx.x << 7;
    float acc[2][8][4];
#pragma unroll
    for (int a = 0; a < 2; a++)
#pragma unroll
        for (int b = 0; b < 8; b++)
#pragma unroll
            for (int c = 0; c < 4; c++) acc[a][b][c] = 0.f;

    mainloop(smem, Ah + (size_t)row0 * K, Al + (size_t)row0 * K, K,
             Bh + (size_t)colb * K, Bl + (size_t)colb * K, K, K >> 5, tid, acc);

    int lane = tid & 31, wid = tid >> 5;
    int g = lane >> 2, tig = lane & 3, wm = wid & 3, wn = wid >> 2;
#pragma unroll
    for (int mt = 0; mt < 2; mt++)
#pragma unroll
        for (int nb = 0; nb < 8; nb++) {
            int gr = row0 + wm * 32 + mt * 16 + g;
            int gc = colb + wn * 64 + nb * 8 + 2 * tig;
            float b0 = 0.f, b1 = 0.f;
            if (bias) { b0 = bias[gc]; b1 = bias[gc + 1]; }
            float* p0 = &C[(size_t)gr * ldc + coloff + gc];
            float* p1 = &C[(size_t)(gr + 8) * ldc + coloff + gc];
            p0[0] = acc[mt][nb][0] + b0; p0[1] = acc[mt][nb][1] + b1;
            p1[0] = acc[mt][nb][2] + b0; p1[1] = acc[mt][nb][3] + b1;
        }
}

__global__ __launch_bounds__(256) void mm_qk() {
    int jt = blockIdx.x, it = blockIdx.y, h = blockIdx.z;
    if (jt > it) return;
    extern __shared__ bf smem[];
    int tid = threadIdx.x;
    int i0 = it << 7, j0 = jt << 7;
    size_t qo = ((size_t)h * SQ + i0) * HDIM;
    size_t ko = ((size_t)(h >> 2) * SQ + j0) * HDIM;
    float acc[2][8][4];
#pragma unroll
    for (int a = 0; a < 2; a++)
#pragma unroll
        for (int b = 0; b < 8; b++)
#pragma unroll
            for (int c = 0; c < 4; c++) acc[a][b][c] = 0.f;

    mainloop(smem, g_q_h + qo, g_q_l + qo, HDIM, g_k_h + ko, g_k_l + ko, HDIM, 4, tid, acc);

    int lane = tid & 31, wid = tid >> 5;
    int g = lane >> 2, tig = lane & 3, wm = wid & 3, wn = wid >> 2;
    const float scale = 0.08838834764831845f;
    float* E = g_e + (size_t)h * SQ * SQ;
#pragma unroll
    for (int mt = 0; mt < 2; mt++)
#pragma unroll
        for (int nb = 0; nb < 8; nb++) {
            int gi = i0 + wm * 32 + mt * 16 + g;
            int gj = j0 + wn * 64 + nb * 8 + 2 * tig;
            if (gj <= gi)     E[(size_t)gi * SQ + gj]     = acc[mt][nb][0] * scale;
            if (gj + 1 <= gi) E[(size_t)gi * SQ + gj + 1] = acc[mt][nb][1] * scale;
            int gi8 = gi + 8;
            if (gj <= gi8)     E[(size_t)gi8 * SQ + gj]     = acc[mt][nb][2] * scale;
            if (gj + 1 <= gi8) E[(size_t)gi8 * SQ + gj + 1] = acc[mt][nb][3] * scale;
        }
}

__global__ __launch_bounds__(256) void mm_av() {
    int qt = blockIdx.x, h = blockIdx.y;
    extern __shared__ bf smem[];
    int tid = threadIdx.x;
    int q0 = qt << 7;
    size_t po = ((size_t)h * SQ + q0) * SQ;
    size_t vo = (size_t)(h >> 2) * HDIM * SQ;
    float acc[2][8][4];
#pragma unroll
    for (int a = 0; a < 2; a++)
#pragma unroll
        for (int b = 0; b < 8; b++)
#pragma unroll
            for (int c = 0; c < 4; c++) acc[a][b][c] = 0.f;

    mainloop(smem, g_p_h + po, g_p_l + po, SQ, g_vT_h + vo, g_vT_l + vo, SQ,
             4 * (qt + 1), tid, acc);

    int lane = tid & 31, wid = tid >> 5;
    int g = lane >> 2, tig = lane & 3, wm = wid & 3, wn = wid >> 2;
#pragma unroll
    for (int mt = 0; mt < 2; mt++)
#pragma unroll
        for (int nb = 0; nb < 8; nb++) {
            int gq = q0 + wm * 32 + mt * 16 + g;
            int gc = wn * 64 + nb * 8 + 2 * tig;
            bf h0, l0, h1, l1;
            split2(acc[mt][nb][0], h0, l0); split2(acc[mt][nb][1], h1, l1);
            size_t o = (size_t)gq * HIDN + (h << 7) + gc;
            *(u32*)(g_ao_h + o) = packbf(h0, h1);
            *(u32*)(g_ao_l + o) = packbf(l0, l1);
            split2(acc[mt][nb][2], h0, l0); split2(acc[mt][nb][3], h1, l1);
            o = (size_t)(gq + 8) * HIDN + (h << 7) + gc;
            *(u32*)(g_ao_h + o) = packbf(h0, h1);
            *(u32*)(g_ao_l + o) = packbf(l0, l1);
        }
}

// ---------------- prep kernels ----------------
__global__ void split_rm(const float* __restrict__ src, bf* __restrict__ h,
                         bf* __restrict__ l, int n) {
    int i = blockIdx.x * blockDim.x + threadIdx.x;
    if (i < n) { bf a, b; split2(src[i], a, b); h[i] = a; l[i] = b; }
}

// W [K x N] fp32 -> dst [N x K] bf16 hi/lo (tiled transpose)
__global__ void split_tr(const float* __restrict__ src, int N,
                         bf* __restrict__ dh, bf* __restrict__ dl, int K) {
    __shared__ float t[32][33];
    int k0 = blockIdx.x << 5, n0 = blockIdx.y << 5;
    int tx = threadIdx.x, ty = threadIdx.y;
#pragma unroll
    for (int r = 0; r < 4; r++)
        t[ty + r * 8][tx] = src[(size_t)(k0 + ty + r * 8) * N + n0 + tx];
    __syncthreads();
#pragma unroll
    for (int r = 0; r < 4; r++) {
        int k = k0 + tx, n = n0 + ty + r * 8;
        bf a, b; split2(t[tx][ty + r * 8], a, b);
        dh[(size_t)n * K + k] = a;
        dl[(size_t)n * K + k] = b;
    }
}

__global__ void rope_kernel(const float* __restrict__ cosp, const float* __restrict__ sinp) {
    int idx = blockIdx.x * blockDim.x + threadIdx.x;
    if (idx >= SQ * QKV_N) return;
    int s = idx / QKV_N, c = idx - s * QKV_N;
    float val = g_qkv[idx];
    if (c < 2048) {
        int h = c >> 7, d = c & 127;
        float cs = cosp[s * HDIM + d], sn = sinp[s * HDIM + d];
        float other = (d < 64) ? -g_qkv[idx + 64] : g_qkv[idx - 64];
        float r = val * cs + other * sn;
        bf a, b; split2(r, a, b);
        size_t o = ((size_t)h * SQ + s) * HDIM + d;
        g_q_h[o] = a; g_q_l[o] = b;
    } else if (c < 2560) {
        int cc = c - 2048, h = cc >> 7, d = cc & 127;
        float cs = cosp[s * HDIM + d], sn = sinp[s * HDIM + d];
        float other = (d < 64) ? -g_qkv[idx + 64] : g_qkv[idx - 64];
        float r = val * cs + other * sn;
        bf a, b; split2(r, a, b);
        size_t o = ((size_t)h * SQ + s) * HDIM + d;
        g_k_h[o] = a; g_k_l[o] = b;
    } else {
        int cc = c - 2560, h = cc >> 7, d = cc & 127;
        g_v[((size_t)h * SQ + s) * HDIM + d] = val;
    }
}

// v [h][s][d] fp32 -> vT [h][d][s] bf16 hi/lo
__global__ void vtsplit_kernel() {
    __shared__ float t[32][33];
    int h = blockIdx.z;
    int s0 = blockIdx.x << 5, d0 = blockIdx.y << 5;
    int tx = threadIdx.x, ty = threadIdx.y;
    const float* V = g_v + (size_t)h * SQ * HDIM;
#pragma unroll
    for (int k = 0; k < 4; k++)
        t[ty + k * 8][tx] = V[(size_t)(s0 + ty + k * 8) * HDIM + d0 + tx];
    __syncthreads();
    bf* oh = g_vT_h + (size_t)h * HDIM * SQ;
    bf* ol = g_vT_l + (size_t)h * HDIM * SQ;
#pragma unroll
    for (int k = 0; k < 4; k++) {
        int d = d0 + ty + k * 8, s = s0 + tx;
        bf a, b; split2(t[tx][ty + k * 8], a, b);
        oh[(size_t)d * SQ + s] = a;
        ol[(size_t)d * SQ + s] = b;
    }
}

// ---------------- softmax / H2O passes ---------------------
__global__ void rowexp_kernel() {
    int i = blockIdx.x, h = blockIdx.y, tid = threadIdx.x;
    float* row = g_e + ((size_t)h * SQ + i) * SQ;
    int n = i + 1;
    float m = -1e30f;
    for (int j = tid; j < n; j += 128) m = fmaxf(m, row[j]);
    __shared__ float red[4];
    m = warp_red_max(m);
    if ((tid & 31) == 0) red[tid >> 5] = m;
    __syncthreads();
    m = fmaxf(fmaxf(red[0], red[1]), fmaxf(red[2], red[3]));
    float ssum = 0.f;
    for (int j = tid; j < n; j += 128) { float e = fexp(row[j] - m); row[j] = e; ssum += e; }
    __syncthreads();
    ssum = warp_red_sum(ssum);
    if ((tid & 31) == 0) red[tid >> 5] = ssum;
    __syncthreads();
    if (tid == 0) g_invrsum[h * SQ + i] = 1.0f / (red[0] + red[1] + red[2] + red[3]);
}

__global__ void colsum_kernel() {
    int h = blockIdx.y;
    int j = blockIdx.x * 256 + threadIdx.x;
    int istart = blockIdx.x * 256;
    const float* E = g_e + (size_t)h * SQ * SQ;
    float acc = 0.f;
    for (int i = istart; i < SQ; i++)
        if (i >= j) acc += E[(size_t)i * SQ + j] * g_invrsum[h * SQ + i];
    g_colsum[h * SQ + j] = acc;
}

__global__ __launch_bounds__(1024) void topk_kernel() {
    __shared__ float sv[2048];
    int h = blockIdx.x, tid = threadIdx.x;
    sv[tid] = g_colsum[h * SQ + tid];
    sv[tid + 1024] = g_colsum[h * SQ + tid + 1024];
    __syncthreads();
    for (int k = 2; k <= 2048; k <<= 1) {
        for (int j = k >> 1; j > 0; j >>= 1) {
#pragma unroll 2
            for (int base = 0; base < 2048; base += 1024) {
                int i = base + tid;
                int l = i ^ j;
                if (l > i) {
                    float a = sv[i], b = sv[l];
                    bool up = ((i & k) == 0);
                    if ((a > b) == up) { sv[i] = b; sv[l] = a; }
                }
            }
            __syncthreads();
        }
    }
    float thr = sv[2048 - HEAVY_K];
    g_heavy[h * SQ + tid]        = (g_colsum[h * SQ + tid]        >= thr) ? 1 : 0;
    g_heavy[h * SQ + tid + 1024] = (g_colsum[h * SQ + tid + 1024] >= thr) ? 1 : 0;
}

// fused: masked row sum + write normalized P (bf16 hi/lo) in one kernel
__global__ void psplit_kernel() {
    int q = blockIdx.x, h = blockIdx.y, tid = threadIdx.x;
    const float* row = g_e + ((size_t)h * SQ + q) * SQ;
    const unsigned char* hv = g_heavy + h * SQ;
    float s = 0.f;
    for (int j = tid; j <= q; j += 256)
        if (hv[j] || (q - j) <= RECENT_W) s += row[j];
    __shared__ float red[8];
    s = warp_red_sum(s);
    if ((tid & 31) == 0) red[tid >> 5] = s;
    __syncthreads();
    float tot = red[0] + red[1] + red[2] + red[3] + red[4] + red[5] + red[6] + red[7];
    float inv = 1.0f / tot;
    int jmax = ((q >> 7) + 1) << 7;
    bf* ph = g_p_h + ((size_t)h * SQ + q) * SQ;
    bf* pl = g_p_l + ((size_t)h * SQ + q) * SQ;
    for (int j = tid; j < jmax; j += 256) {
        float p = 0.f;
        if (j <= q && (hv[j] || (q - j) <= RECENT_W)) p = row[j] * inv;
        bf a, b; split2(p, a, b);
        ph[j] = a; pl[j] = b;
    }
}

// ---------------- launch ----------------
extern "C" void kernel_launch(void* const* d_in, const int* in_sizes, int n_in,
                              void* d_out, int out_size) {
    (void)in_sizes; (void)n_in; (void)out_size;
    const float* hidden = (const float*)d_in[0];
    const float* cosp   = (const float*)d_in[1];
    const float* sinp   = (const float*)d_in[2];
    const float* Wq = (const float*)d_in[4];
    const float* bq = (const float*)d_in[5];
    const float* Wk = (const float*)d_in[6];
    const float* bk = (const float*)d_in[7];
    const float* Wv = (const float*)d_in[8];
    const float* bv = (const float*)d_in[9];
    const float* Wo = (const float*)d_in[10];
    float* out = (float*)d_out;

    cudaFuncSetAttribute(mm_lin, cudaFuncAttributeMaxDynamicSharedMemorySize, SMEMB);
    cudaFuncSetAttribute(mm_qk,  cudaFuncAttributeMaxDynamicSharedMemorySize, SMEMB);
    cudaFuncSetAttribute(mm_av,  cudaFuncAttributeMaxDynamicSharedMemorySize, SMEMB);

    void* p;
    cudaGetSymbolAddress(&p, g_qkv);   float* qkv  = (float*)p;
    cudaGetSymbolAddress(&p, g_hid_h); bf* hid_h = (bf*)p;
    cudaGetSymbolAddress(&p, g_hid_l); bf* hid_l = (bf*)p;
    cudaGetSymbolAddress(&p, g_wT_h);  bf* wT_h  = (bf*)p;
    cudaGetSymbolAddress(&p, g_wT_l);  bf* wT_l  = (bf*)p;
    cudaGetSymbolAddress(&p, g_woT_h); bf* woT_h = (bf*)p;
    cudaGetSymbolAddress(&p, g_woT_l); bf* woT_l = (bf*)p;
    cudaGetSymbolAddress(&p, g_ao_h);  bf* ao_h  = (bf*)p;
    cudaGetSymbolAddress(&p, g_ao_l);  bf* ao_l  = (bf*)p;

    // split inputs / transpose weights to K-major bf16 hi/lo
    split_rm<<<(SQ * HIDN + 1023) / 1024, 1024>>>(hidden, hid_h, hid_l, SQ * HIDN);
    split_tr<<<dim3(64, 64), dim3(32, 8)>>>(Wq, 2048, wT_h, wT_l, HIDN);
    split_tr<<<dim3(64, 16), dim3(32, 8)>>>(Wk, 512, wT_h + (size_t)2048 * HIDN, wT_l + (size_t)2048 * HIDN, HIDN);
    split_tr<<<dim3(64, 16), dim3(32, 8)>>>(Wv, 512, wT_h + (size_t)2560 * HIDN, wT_l + (size_t)2560 * HIDN, HIDN);
    split_tr<<<dim3(64, 64), dim3(32, 8)>>>(Wo, 2048, woT_h, woT_l, HIDN);

    // QKV projections (tensor cores, mma.sync bf16x3)
    mm_lin<<<dim3(16, 16), 256, SMEMB>>>(hid_h, hid_l, wT_h, wT_l, HIDN, qkv, QKV_N, 0, bq);
    mm_lin<<<dim3(4, 16), 256, SMEMB>>>(hid_h, hid_l, wT_h + (size_t)2048 * HIDN, wT_l + (size_t)2048 * HIDN, HIDN, qkv, QKV_N, 2048, bk);
    mm_lin<<<dim3(4, 16), 256, SMEMB>>>(hid_h, hid_l, wT_h + (size_t)2560 * HIDN, wT_l + (size_t)2560 * HIDN, HIDN, qkv, QKV_N, 2560, bv);

    rope_kernel<<<(SQ * QKV_N + 255) / 256, 256>>>(cosp, sinp);
    vtsplit_kernel<<<dim3(64, 4, NKVH), dim3(32, 8)>>>();

    mm_qk<<<dim3(16, 16, NHEAD), 256, SMEMB>>>();
    rowexp_kernel<<<dim3(SQ, NHEAD), 128>>>();
    colsum_kernel<<<dim3(8, NHEAD), 256>>>();
    topk_kernel<<<NHEAD, 1024>>>();
    psplit_kernel<<<dim3(SQ, NHEAD), 256>>>();
    mm_av<<<dim3(16, NHEAD), 256, SMEMB>>>();

    // output projection
    mm_lin<<<dim3(16, 16), 256, SMEMB>>>(ao_h, ao_l, woT_h, woT_l, HIDN, out, HIDN, 0, (const float*)nullptr);
}

// round 15
// speedup vs baseline: 2.2881x; 1.0510x over previous
#include <cuda_runtime.h>
#include <cuda_bf16.h>
#include <cstdint>
#include <cstddef>

#define SQ 2048
#define HIDN 2048
#define NHEAD 16
#define NKVH 4
#define HDIM 128
#define QKV_N 3072
#define RECENT_W 204
#define HEAVY_K 204

typedef __nv_bfloat16 bf;
typedef unsigned int u32;

// ---------------- device globals (no allocations allowed) -------------------
__device__ __align__(16) float g_qkv[SQ * QKV_N];
__device__ __align__(16) bf g_hid_h[SQ * HIDN];
__device__ __align__(16) bf g_hid_l[SQ * HIDN];
__device__ __align__(16) bf g_wT_h[(size_t)QKV_N * HIDN];
__device__ __align__(16) bf g_wT_l[(size_t)QKV_N * HIDN];
__device__ __align__(16) bf g_woT_h[(size_t)HIDN * HIDN];
__device__ __align__(16) bf g_woT_l[(size_t)HIDN * HIDN];
__device__ __align__(16) bf g_q_h[NHEAD * SQ * HDIM];
__device__ __align__(16) bf g_q_l[NHEAD * SQ * HDIM];
__device__ __align__(16) bf g_k_h[NKVH * SQ * HDIM];
__device__ __align__(16) bf g_k_l[NKVH * SQ * HDIM];
__device__ __align__(16) float g_v[NKVH * SQ * HDIM];
__device__ __align__(16) bf g_vT_h[NKVH * HDIM * SQ];
__device__ __align__(16) bf g_vT_l[NKVH * HDIM * SQ];
__device__ __align__(16) float g_e[(size_t)NHEAD * SQ * SQ];
__device__ __align__(16) bf g_p_h[(size_t)NHEAD * SQ * SQ];
__device__ __align__(16) bf g_p_l[(size_t)NHEAD * SQ * SQ];
__device__ __align__(16) bf g_ao_h[SQ * HIDN];
__device__ __align__(16) bf g_ao_l[SQ * HIDN];
__device__ float g_bias[QKV_N];
__device__ float g_invrsum[NHEAD * SQ];
__device__ float g_colsum[NHEAD * SQ];
__device__ unsigned char g_heavy[NHEAD * SQ];

// ---------------- small helpers ----------------
static __device__ __forceinline__ void split2(float x, bf& h, bf& l) {
    h = __float2bfloat16_rn(x);
    l = __float2bfloat16_rn(x - __bfloat162float(h));
}
static __device__ __forceinline__ u32 packbf(bf a, bf b) {
    return (u32)__bfloat16_as_ushort(a) | ((u32)__bfloat16_as_ushort(b) << 16);
}
static __device__ __forceinline__ float warp_red_max(float v) {
#pragma unroll
    for (int o = 16; o > 0; o >>= 1) v = fmaxf(v, __shfl_xor_sync(0xffffffffu, v, o));
    return v;
}
static __device__ __forceinline__ float warp_red_sum(float v) {
#pragma unroll
    for (int o = 16; o > 0; o >>= 1) v += __shfl_xor_sync(0xffffffffu, v, o);
    return v;
}
// fast exp for x <= 0: FFMA-pipe polynomial (error ~1.3e-6 rel), no MUFU.
static __device__ __forceinline__ float fexp(float x) {
    float y = x * 1.4426950408889634f;         // log2(e)
    if (y < -126.0f) return 0.0f;
    float f = floorf(y);
    float r = y - f;
    float p = 1.525273380405984e-5f;
    p = fmaf(p, r, 1.5403530393381608e-4f);
    p = fmaf(p, r, 1.3333558146428443e-3f);
    p = fmaf(p, r, 9.618129107628477e-3f);
    p = fmaf(p, r, 5.550410866482158e-2f);
    p = fmaf(p, r, 2.4022650695910072e-1f);
    p = fmaf(p, r, 6.931471805599453e-1f);
    p = fmaf(p, r, 1.0f);
    float sc = __int_as_float(((int)f + 127) << 23);
    return sc * p;
}

// ---------------- mma.sync m16n8k16 bf16 (baseline PTX, sm_80+) -----------
static __device__ __forceinline__ void mma_tile(float* d, const u32* a, u32 b0, u32 b1) {
    asm volatile(
        "mma.sync.aligned.m16n8k16.row.col.f32.bf16.bf16.f32 "
        "{%0,%1,%2,%3}, {%4,%5,%6,%7}, {%8,%9}, {%0,%1,%2,%3};"
        : "+f"(d[0]), "+f"(d[1]), "+f"(d[2]), "+f"(d[3])
        : "r"(a[0]), "r"(a[1]), "r"(a[2]), "r"(a[3]), "r"(b0), "r"(b1));
}
static __device__ __forceinline__ void ldsm_x4(u32* r, u32 addr) {
    asm volatile("ldmatrix.sync.aligned.m8n8.x4.shared.b16 {%0,%1,%2,%3}, [%4];"
        : "=r"(r[0]), "=r"(r[1]), "=r"(r[2]), "=r"(r[3]) : "r"(addr));
}
static __device__ __forceinline__ u32 smem_u32(const void* p) {
    u32 a;
    asm("{ .reg .u64 t; cvta.to.shared.u64 t, %1; cvt.u32.u64 %0, t; }" : "=r"(a) : "l"(p));
    return a;
}
static __device__ __forceinline__ void cp16(u32 dst, const void* src) {
    asm volatile("cp.async.cg.shared.global [%0], [%1], 16;" :: "r"(dst), "l"(src));
}
#define CP_COMMIT() asm volatile("cp.async.commit_group;" ::: "memory")
#define CP_WAIT1() asm volatile("cp.async.wait_group 1;" ::: "memory")
#define CP_WAIT0() asm volatile("cp.async.wait_group 0;" ::: "memory")

// ---------------- bf16x3 GEMM mainloop ------------------------------------
// Block tile 128x128, K-chunk 32, 3-stage cp.async ring (padded stride 40),
// 8 warps in 4(M)x2(N) layout, warp tile 32x64, ldmatrix fragment loads.
#define TP 40
#define TILEE (128 * TP)             // elements per tile
#define TILEB (TILEE * 2)            // bytes per tile = 10240
#define STAGEB (4 * TILEB)           // bytes per stage = 40960
#define SMEMB (3 * STAGEB)           // 122880 bytes

static __device__ __forceinline__ void issue_chunk(
    u32 sdst, const bf* Ah, const bf* Al, int lda,
    const bf* Bh, const bf* Bl, int ldb, int k0, int r, int halfe)
{
    const bf* a0 = Ah + (size_t)r * lda + k0 + halfe;
    const bf* a1 = Al + (size_t)r * lda + k0 + halfe;
    const bf* b0 = Bh + (size_t)r * ldb + k0 + halfe;
    const bf* b1 = Bl + (size_t)r * ldb + k0 + halfe;
    u32 so = sdst + (u32)((r * TP + halfe) << 1);
    cp16(so,             a0); cp16(so + 16,             a0 + 8);
    cp16(so + TILEB,     a1); cp16(so + TILEB + 16,     a1 + 8);
    cp16(so + 2 * TILEB, b0); cp16(so + 2 * TILEB + 16, b0 + 8);
    cp16(so + 3 * TILEB, b1); cp16(so + 3 * TILEB + 16, b1 + 8);
}

static __device__ __forceinline__ void mainloop(
    bf* smem,
    const bf* __restrict__ Ah, const bf* __restrict__ Al, int lda,
    const bf* __restrict__ Bh, const bf* __restrict__ Bl, int ldb,
    int nchunk, int tid, float acc[2][8][4])
{
    int r = tid >> 1, halfe = (tid & 1) << 4;
    int lane = tid & 31, wid = tid >> 5;
    int wm = wid & 3, wn = wid >> 2;
    u32 sbase = smem_u32(smem);
    // ldmatrix per-lane offsets (bytes)
    u32 aoff = (u32)(((lane & 15) * TP + ((lane >> 4) << 3)) << 1);
    u32 boff = (u32)(((((lane & 7) + ((lane >> 4) << 3)) * TP) + (((lane >> 3) & 1) << 3)) << 1);
    u32 aA0 = sbase + aoff + (u32)((wm * 32 * TP) << 1);
    u32 bB0 = sbase + (u32)(2 * TILEB) + boff + (u32)((wn * 64 * TP) << 1);

    issue_chunk(sbase, Ah, Al, lda, Bh, Bl, ldb, 0, r, halfe);
    CP_COMMIT();
    if (nchunk > 1) {
        issue_chunk(sbase + STAGEB, Ah, Al, lda, Bh, Bl, ldb, 32, r, halfe);
        CP_COMMIT();
    }

    int stg = 0;
    for (int c = 0; c < nchunk; c++) {
        if (c + 1 < nchunk) { CP_WAIT1(); } else { CP_WAIT0(); }
        __syncthreads();
        if (c + 2 < nchunk) {
            int ns = stg + 2; if (ns >= 3) ns -= 3;
            issue_chunk(sbase + (u32)(ns * STAGEB), Ah, Al, lda, Bh, Bl, ldb,
                        (c + 2) << 5, r, halfe);
            CP_COMMIT();
        }
        u32 stb = (u32)(stg * STAGEB);
#pragma unroll
        for (int ks = 0; ks < 32; ks += 16) {
            u32 ah[2][4], al[2][4];
#pragma unroll
            for (int mt = 0; mt < 2; mt++) {
                u32 ad = aA0 + stb + (u32)(((mt * 16 * TP) + ks) << 1);
                ldsm_x4(ah[mt], ad);
                ldsm_x4(al[mt], ad + (u32)TILEB);
            }
#pragma unroll
            for (int nbp = 0; nbp < 4; nbp++) {
                u32 bd = bB0 + stb + (u32)(((nbp * 16 * TP) + ks) << 1);
                u32 bh[4], bl[4];
                ldsm_x4(bh, bd);
                ldsm_x4(bl, bd + (u32)TILEB);
#pragma unroll
                for (int hh = 0; hh < 2; hh++) {
                    int nb = nbp * 2 + hh;
                    u32 b0h = bh[hh * 2], b1h = bh[hh * 2 + 1];
                    u32 b0l = bl[hh * 2], b1l = bl[hh * 2 + 1];
#pragma unroll
                    for (int mt = 0; mt < 2; mt++) {
                        mma_tile(acc[mt][nb], ah[mt], b0h, b1h);
                        mma_tile(acc[mt][nb], al[mt], b0h, b1h);
                        mma_tile(acc[mt][nb], ah[mt], b0l, b1l);
                    }
                }
            }
        }
        stg++; if (stg == 3) stg = 0;
    }
}

// ---------------- GEMM kernels ----------------
__global__ __launch_bounds__(256) void mm_lin(
    const bf* __restrict__ Ah, const bf* __restrict__ Al,
    const bf* __restrict__ Bh, const bf* __restrict__ Bl,
    int K, float* __restrict__ C, int ldc, int coloff, const float* __restrict__ bias)
{
    extern __shared__ bf smem[];
    int tid = threadIdx.x;
    int row0 = blockIdx.y << 7, colb = blockIdx.x << 7;
    float acc[2][8][4];
#pragma unroll
    for (int a = 0; a < 2; a++)
#pragma unroll
        for (int b = 0; b < 8; b++)
#pragma unroll
            for (int c = 0; c < 4; c++) acc[a][b][c] = 0.f;

    mainloop(smem, Ah + (size_t)row0 * K, Al + (size_t)row0 * K, K,
             Bh + (size_t)colb * K, Bl + (size_t)colb * K, K, K >> 5, tid, acc);

    int lane = tid & 31, wid = tid >> 5;
    int g = lane >> 2, tig = lane & 3, wm = wid & 3, wn = wid >> 2;
#pragma unroll
    for (int mt = 0; mt < 2; mt++)
#pragma unroll
        for (int nb = 0; nb < 8; nb++) {
            int gr = row0 + wm * 32 + mt * 16 + g;
            int gc = colb + wn * 64 + nb * 8 + 2 * tig;
            float b0 = 0.f, b1 = 0.f;
            if (bias) { b0 = bias[gc]; b1 = bias[gc + 1]; }
            float* p0 = &C[(size_t)gr * ldc + coloff + gc];
            float* p1 = &C[(size_t)(gr + 8) * ldc + coloff + gc];
            p0[0] = acc[mt][nb][0] + b0; p0[1] = acc[mt][nb][1] + b1;
            p1[0] = acc[mt][nb][2] + b0; p1[1] = acc[mt][nb][3] + b1;
        }
}

__global__ __launch_bounds__(256) void mm_qk() {
    int jt = blockIdx.x, it = blockIdx.y, h = blockIdx.z;
    if (jt > it) return;
    extern __shared__ bf smem[];
    int tid = threadIdx.x;
    int i0 = it << 7, j0 = jt << 7;
    size_t qo = ((size_t)h * SQ + i0) * HDIM;
    size_t ko = ((size_t)(h >> 2) * SQ + j0) * HDIM;
    float acc[2][8][4];
#pragma unroll
    for (int a = 0; a < 2; a++)
#pragma unroll
        for (int b = 0; b < 8; b++)
#pragma unroll
            for (int c = 0; c < 4; c++) acc[a][b][c] = 0.f;

    mainloop(smem, g_q_h + qo, g_q_l + qo, HDIM, g_k_h + ko, g_k_l + ko, HDIM, 4, tid, acc);

    int lane = tid & 31, wid = tid >> 5;
    int g = lane >> 2, tig = lane & 3, wm = wid & 3, wn = wid >> 2;
    const float scale = 0.08838834764831845f;
    float* E = g_e + (size_t)h * SQ * SQ;
#pragma unroll
    for (int mt = 0; mt < 2; mt++)
#pragma unroll
        for (int nb = 0; nb < 8; nb++) {
            int gi = i0 + wm * 32 + mt * 16 + g;
            int gj = j0 + wn * 64 + nb * 8 + 2 * tig;
            if (gj <= gi)     E[(size_t)gi * SQ + gj]     = acc[mt][nb][0] * scale;
            if (gj + 1 <= gi) E[(size_t)gi * SQ + gj + 1] = acc[mt][nb][1] * scale;
            int gi8 = gi + 8;
            if (gj <= gi8)     E[(size_t)gi8 * SQ + gj]     = acc[mt][nb][2] * scale;
            if (gj + 1 <= gi8) E[(size_t)gi8 * SQ + gj + 1] = acc[mt][nb][3] * scale;
        }
}

__global__ __launch_bounds__(256) void mm_av() {
    int qt = blockIdx.x, h = blockIdx.y;
    extern __shared__ bf smem[];
    int tid = threadIdx.x;
    int q0 = qt << 7;
    size_t po = ((size_t)h * SQ + q0) * SQ;
    size_t vo = (size_t)(h >> 2) * HDIM * SQ;
    float acc[2][8][4];
#pragma unroll
    for (int a = 0; a < 2; a++)
#pragma unroll
        for (int b = 0; b < 8; b++)
#pragma unroll
            for (int c = 0; c < 4; c++) acc[a][b][c] = 0.f;

    mainloop(smem, g_p_h + po, g_p_l + po, SQ, g_vT_h + vo, g_vT_l + vo, SQ,
             4 * (qt + 1), tid, acc);

    int lane = tid & 31, wid = tid >> 5;
    int g = lane >> 2, tig = lane & 3, wm = wid & 3, wn = wid >> 2;
#pragma unroll
    for (int mt = 0; mt < 2; mt++)
#pragma unroll
        for (int nb = 0; nb < 8; nb++) {
            int gq = q0 + wm * 32 + mt * 16 + g;
            int gc = wn * 64 + nb * 8 + 2 * tig;
            bf h0, l0, h1, l1;
            split2(acc[mt][nb][0], h0, l0); split2(acc[mt][nb][1], h1, l1);
            size_t o = (size_t)gq * HIDN + (h << 7) + gc;
            *(u32*)(g_ao_h + o) = packbf(h0, h1);
            *(u32*)(g_ao_l + o) = packbf(l0, l1);
            split2(acc[mt][nb][2], h0, l0); split2(acc[mt][nb][3], h1, l1);
            o = (size_t)(gq + 8) * HIDN + (h << 7) + gc;
            *(u32*)(g_ao_h + o) = packbf(h0, h1);
            *(u32*)(g_ao_l + o) = packbf(l0, l1);
        }
}

// ---------------- prep kernels ----------------
__global__ void split_rm(const float* __restrict__ src, bf* __restrict__ h,
                         bf* __restrict__ l, int n) {
    int i = blockIdx.x * blockDim.x + threadIdx.x;
    if (i < n) { bf a, b; split2(src[i], a, b); h[i] = a; l[i] = b; }
}

__global__ void catb_kernel(const float* __restrict__ bq, const float* __restrict__ bk,
                            const float* __restrict__ bv) {
    int i = blockIdx.x * blockDim.x + threadIdx.x;
    if (i < 2048) g_bias[i] = bq[i];
    else if (i < 2560) g_bias[i] = bk[i - 2048];
    else if (i < QKV_N) g_bias[i] = bv[i - 2560];
}

// W [K x N] fp32 -> dst [N x K] bf16 hi/lo (tiled transpose)
__global__ void split_tr(const float* __restrict__ src, int N,
                         bf* __restrict__ dh, bf* __restrict__ dl, int K) {
    __shared__ float t[32][33];
    int k0 = blockIdx.x << 5, n0 = blockIdx.y << 5;
    int tx = threadIdx.x, ty = threadIdx.y;
#pragma unroll
    for (int r = 0; r < 4; r++)
        t[ty + r * 8][tx] = src[(size_t)(k0 + ty + r * 8) * N + n0 + tx];
    __syncthreads();
#pragma unroll
    for (int r = 0; r < 4; r++) {
        int k = k0 + tx, n = n0 + ty + r * 8;
        bf a, b; split2(t[tx][ty + r * 8], a, b);
        dh[(size_t)n * K + k] = a;
        dl[(size_t)n * K + k] = b;
    }
}

__global__ void rope_kernel(const float* __restrict__ cosp, const float* __restrict__ sinp) {
    int idx = blockIdx.x * blockDim.x + threadIdx.x;
    if (idx >= SQ * QKV_N) return;
    int s = idx / QKV_N, c = idx - s * QKV_N;
    float val = g_qkv[idx];
    if (c < 2048) {
        int h = c >> 7, d = c & 127;
        float cs = cosp[s * HDIM + d], sn = sinp[s * HDIM + d];
        float other = (d < 64) ? -g_qkv[idx + 64] : g_qkv[idx - 64];
        float r = val * cs + other * sn;
        bf a, b; split2(r, a, b);
        size_t o = ((size_t)h * SQ + s) * HDIM + d;
        g_q_h[o] = a; g_q_l[o] = b;
    } else if (c < 2560) {
        int cc = c - 2048, h = cc >> 7, d = cc & 127;
        float cs = cosp[s * HDIM + d], sn = sinp[s * HDIM + d];
        float other = (d < 64) ? -g_qkv[idx + 64] : g_qkv[idx - 64];
        float r = val * cs + other * sn;
        bf a, b; split2(r, a, b);
        size_t o = ((size_t)h * SQ + s) * HDIM + d;
        g_k_h[o] = a; g_k_l[o] = b;
    } else {
        int cc = c - 2560, h = cc >> 7, d = cc & 127;
        g_v[((size_t)h * SQ + s) * HDIM + d] = val;
    }
}

// v [h][s][d] fp32 -> vT [h][d][s] bf16 hi/lo
__global__ void vtsplit_kernel() {
    __shared__ float t[32][33];
    int h = blockIdx.z;
    int s0 = blockIdx.x << 5, d0 = blockIdx.y << 5;
    int tx = threadIdx.x, ty = threadIdx.y;
    const float* V = g_v + (size_t)h * SQ * HDIM;
#pragma unroll
    for (int k = 0; k < 4; k++)
        t[ty + k * 8][tx] = V[(size_t)(s0 + ty + k * 8) * HDIM + d0 + tx];
    __syncthreads();
    bf* oh = g_vT_h + (size_t)h * HDIM * SQ;
    bf* ol = g_vT_l + (size_t)h * HDIM * SQ;
#pragma unroll
    for (int k = 0; k < 4; k++) {
        int d = d0 + ty + k * 8, s = s0 + tx;
        bf a, b; split2(t[tx][ty + k * 8], a, b);
        oh[(size_t)d * SQ + s] = a;
        ol[(size_t)d * SQ + s] = b;
    }
}

// ---------------- softmax / H2O passes ---------------------
__global__ void rowexp_kernel() {
    int i = blockIdx.x, h = blockIdx.y, tid = threadIdx.x;
    float* row = g_e + ((size_t)h * SQ + i) * SQ;
    int n = i + 1;
    float m = -1e30f;
    for (int j = tid; j < n; j += 128) m = fmaxf(m, row[j]);
    __shared__ float red[4];
    m = warp_red_max(m);
    if ((tid & 31) == 0) red[tid >> 5] = m;
    __syncthreads();
    m = fmaxf(fmaxf(red[0], red[1]), fmaxf(red[2], red[3]));
    float ssum = 0.f;
    for (int j = tid; j < n; j += 128) { float e = fexp(row[j] - m); row[j] = e; ssum += e; }
    __syncthreads();
    ssum = warp_red_sum(ssum);
    if ((tid & 31) == 0) red[tid >> 5] = ssum;
    __syncthreads();
    if (tid == 0) g_invrsum[h * SQ + i] = 1.0f / (red[0] + red[1] + red[2] + red[3]);
}

__global__ void colsum_kernel() {
    int h = blockIdx.y;
    int j = blockIdx.x * 256 + threadIdx.x;
    int istart = blockIdx.x * 256;
    const float* E = g_e + (size_t)h * SQ * SQ;
    float acc = 0.f;
    for (int i = istart; i < SQ; i++)
        if (i >= j) acc += E[(size_t)i * SQ + j] * g_invrsum[h * SQ + i];
    g_colsum[h * SQ + j] = acc;
}

__global__ __launch_bounds__(1024) void topk_kernel() {
    __shared__ float sv[2048];
    int h = blockIdx.x, tid = threadIdx.x;
    sv[tid] = g_colsum[h * SQ + tid];
    sv[tid + 1024] = g_colsum[h * SQ + tid + 1024];
    __syncthreads();
    for (int k = 2; k <= 2048; k <<= 1) {
        for (int j = k >> 1; j > 0; j >>= 1) {
#pragma unroll 2
            for (int base = 0; base < 2048; base += 1024) {
                int i = base + tid;
                int l = i ^ j;
                if (l > i) {
                    float a = sv[i], b = sv[l];
                    bool up = ((i & k) == 0);
                    if ((a > b) == up) { sv[i] = b; sv[l] = a; }
                }
            }
            __syncthreads();
        }
    }
    float thr = sv[2048 - HEAVY_K];
    g_heavy[h * SQ + tid]        = (g_colsum[h * SQ + tid]        >= thr) ? 1 : 0;
    g_heavy[h * SQ + tid + 1024] = (g_colsum[h * SQ + tid + 1024] >= thr) ? 1 : 0;
}

// fused: masked row sum + write normalized P (bf16 hi/lo) in one kernel
__global__ void psplit_kernel() {
    int q = blockIdx.x, h = blockIdx.y, tid = threadIdx.x;
    const float* row = g_e + ((size_t)h * SQ + q) * SQ;
    const unsigned char* hv = g_heavy + h * SQ;
    float s = 0.f;
    for (int j = tid; j <= q; j += 256)
        if (hv[j] || (q - j) <= RECENT_W) s += row[j];
    __shared__ float red[8];
    s = warp_red_sum(s);
    if ((tid & 31) == 0) red[tid >> 5] = s;
    __syncthreads();
    float tot = red[0] + red[1] + red[2] + red[3] + red[4] + red[5] + red[6] + red[7];
    float inv = 1.0f / tot;
    int jmax = ((q >> 7) + 1) << 7;
    bf* ph = g_p_h + ((size_t)h * SQ + q) * SQ;
    bf* pl = g_p_l + ((size_t)h * SQ + q) * SQ;
    for (int j = tid; j < jmax; j += 256) {
        float p = 0.f;
        if (j <= q && (hv[j] || (q - j) <= RECENT_W)) p = row[j] * inv;
        bf a, b; split2(p, a, b);
        ph[j] = a; pl[j] = b;
    }
}

// ---------------- launch ----------------
extern "C" void kernel_launch(void* const* d_in, const int* in_sizes, int n_in,
                              void* d_out, int out_size) {
    (void)in_sizes; (void)n_in; (void)out_size;
    const float* hidden = (const float*)d_in[0];
    const float* cosp   = (const float*)d_in[1];
    const float* sinp   = (const float*)d_in[2];
    const float* Wq = (const float*)d_in[4];
    const float* bq = (const float*)d_in[5];
    const float* Wk = (const float*)d_in[6];
    const float* bk = (const float*)d_in[7];
    const float* Wv = (const float*)d_in[8];
    const float* bv = (const float*)d_in[9];
    const float* Wo = (const float*)d_in[10];
    float* out = (float*)d_out;

    cudaFuncSetAttribute(mm_lin, cudaFuncAttributeMaxDynamicSharedMemorySize, SMEMB);
    cudaFuncSetAttribute(mm_qk,  cudaFuncAttributeMaxDynamicSharedMemorySize, SMEMB);
    cudaFuncSetAttribute(mm_av,  cudaFuncAttributeMaxDynamicSharedMemorySize, SMEMB);

    void* p;
    cudaGetSymbolAddress(&p, g_qkv);   float* qkv  = (float*)p;
    cudaGetSymbolAddress(&p, g_hid_h); bf* hid_h = (bf*)p;
    cudaGetSymbolAddress(&p, g_hid_l); bf* hid_l = (bf*)p;
    cudaGetSymbolAddress(&p, g_wT_h);  bf* wT_h  = (bf*)p;
    cudaGetSymbolAddress(&p, g_wT_l);  bf* wT_l  = (bf*)p;
    cudaGetSymbolAddress(&p, g_woT_h); bf* woT_h = (bf*)p;
    cudaGetSymbolAddress(&p, g_woT_l); bf* woT_l = (bf*)p;
    cudaGetSymbolAddress(&p, g_ao_h);  bf* ao_h  = (bf*)p;
    cudaGetSymbolAddress(&p, g_ao_l);  bf* ao_l  = (bf*)p;
    cudaGetSymbolAddress(&p, g_bias);  float* biasq = (float*)p;

    // split inputs / transpose weights to K-major bf16 hi/lo
    split_rm<<<(SQ * HIDN + 1023) / 1024, 1024>>>(hidden, hid_h, hid_l, SQ * HIDN);
    catb_kernel<<<3, 1024>>>(bq, bk, bv);
    split_tr<<<dim3(64, 64), dim3(32, 8)>>>(Wq, 2048, wT_h, wT_l, HIDN);
    split_tr<<<dim3(64, 16), dim3(32, 8)>>>(Wk, 512, wT_h + (size_t)2048 * HIDN, wT_l + (size_t)2048 * HIDN, HIDN);
    split_tr<<<dim3(64, 16), dim3(32, 8)>>>(Wv, 512, wT_h + (size_t)2560 * HIDN, wT_l + (size_t)2560 * HIDN, HIDN);
    split_tr<<<dim3(64, 64), dim3(32, 8)>>>(Wo, 2048, woT_h, woT_l, HIDN);

    // fused QKV projection (tensor cores, mma.sync bf16x3)
    mm_lin<<<dim3(24, 16), 256, SMEMB>>>(hid_h, hid_l, wT_h, wT_l, HIDN, qkv, QKV_N, 0, biasq);

    rope_kernel<<<(SQ * QKV_N + 255) / 256, 256>>>(cosp, sinp);
    vtsplit_kernel<<<dim3(64, 4, NKVH), dim3(32, 8)>>>();

    mm_qk<<<dim3(16, 16, NHEAD), 256, SMEMB>>>();
    rowexp_kernel<<<dim3(SQ, NHEAD), 128>>>();
    colsum_kernel<<<dim3(8, NHEAD), 256>>>();
    topk_kernel<<<NHEAD, 1024>>>();
    psplit_kernel<<<dim3(SQ, NHEAD), 256>>>();
    mm_av<<<dim3(16, NHEAD), 256, SMEMB>>>();

    // output projection
    mm_lin<<<dim3(16, 16), 256, SMEMB>>>(ao_h, ao_l, woT_h, woT_l, HIDN, out, HIDN, 0, (const float*)nullptr);
}